// round 1
// baseline (speedup 1.0000x reference)
#include <cuda_runtime.h>

// Problem constants
#define CB 2
#define CT 2048
#define CD 1024
#define CNH 16
#define CHD 64
#define CM (CB*CT)              // 4096 rows

// Scratch (device globals: no allocation allowed in kernel_launch)
__device__ float g_q[CB*CNH*CT*CHD];
__device__ float g_k[CB*CNH*CT*CHD];
__device__ float g_v[CB*CNH*CT*CHD];
__device__ float g_att[CB*CT*CD];

// ---------------------------------------------------------------------------
// GEMM: C[M,N] = A[M,K] @ W[N,K]^T + bias, then *scale.
// headmajor=1: dst laid out [B, NH, T, HD]; headmajor=0: dst [M, N] row-major.
// Block 128x128, BK=16, 256 threads, 8x8 per-thread tile.
// ---------------------------------------------------------------------------
__global__ __launch_bounds__(256, 2)
void gemm_kernel(const float* __restrict__ A, const float* __restrict__ W,
                 const float* __restrict__ bias, float* __restrict__ dst,
                 float scale, int headmajor)
{
    __shared__ float As[16][132];
    __shared__ float Ws[16][132];

    const int tid = threadIdx.x;
    const int bm  = blockIdx.y * 128;
    const int bn  = blockIdx.x * 128;
    const int lr  = tid >> 2;            // 0..63 (load row)
    const int lc  = (tid & 3) * 4;       // 0,4,8,12 (load col group)
    const int tx  = (tid & 15) * 8;      // C col offset
    const int ty  = (tid >> 4) * 8;      // C row offset

    const float* Ap = A + (size_t)(bm + lr) * CD + lc;
    const float* Wp = W + (size_t)(bn + lr) * CD + lc;

    float acc[8][8];
    #pragma unroll
    for (int i = 0; i < 8; i++)
        #pragma unroll
        for (int j = 0; j < 8; j++) acc[i][j] = 0.f;

    for (int k0 = 0; k0 < CD; k0 += 16) {
        float4 a0 = *(const float4*)(Ap + k0);
        float4 a1 = *(const float4*)(Ap + (size_t)64 * CD + k0);
        float4 w0 = *(const float4*)(Wp + k0);
        float4 w1 = *(const float4*)(Wp + (size_t)64 * CD + k0);
        __syncthreads();
        As[lc+0][lr]    = a0.x; As[lc+1][lr]    = a0.y; As[lc+2][lr]    = a0.z; As[lc+3][lr]    = a0.w;
        As[lc+0][lr+64] = a1.x; As[lc+1][lr+64] = a1.y; As[lc+2][lr+64] = a1.z; As[lc+3][lr+64] = a1.w;
        Ws[lc+0][lr]    = w0.x; Ws[lc+1][lr]    = w0.y; Ws[lc+2][lr]    = w0.z; Ws[lc+3][lr]    = w0.w;
        Ws[lc+0][lr+64] = w1.x; Ws[lc+1][lr+64] = w1.y; Ws[lc+2][lr+64] = w1.z; Ws[lc+3][lr+64] = w1.w;
        __syncthreads();

        #pragma unroll
        for (int kk = 0; kk < 16; kk++) {
            float av[8], bv[8];
            *(float4*)(av)     = *(const float4*)&As[kk][ty];
            *(float4*)(av + 4) = *(const float4*)&As[kk][ty + 4];
            *(float4*)(bv)     = *(const float4*)&Ws[kk][tx];
            *(float4*)(bv + 4) = *(const float4*)&Ws[kk][tx + 4];
            #pragma unroll
            for (int i = 0; i < 8; i++)
                #pragma unroll
                for (int j = 0; j < 8; j++)
                    acc[i][j] += av[i] * bv[j];
        }
    }

    #pragma unroll
    for (int j = 0; j < 8; j++) {
        const int n = bn + tx + j;
        const float bb = bias[n];
        const int h = n >> 6;
        const int d = n & 63;
        #pragma unroll
        for (int i = 0; i < 8; i++) {
            const int m = bm + ty + i;
            const float v = (acc[i][j] + bb) * scale;
            if (headmajor) {
                const int b = m >> 11;          // T = 2048
                const int t = m & (CT - 1);
                g_q[0]; // no-op keepalive (optimized away)
                dst[((size_t)((b * CNH + h) * CT + t) << 6) + d] = v;
            } else {
                dst[(size_t)m * CD + n] = v;
            }
        }
    }
}

// ---------------------------------------------------------------------------
// Flash attention with ALiBi + causal.
// Grid: (T/32, NH, B). 128 threads (4 warps), each warp owns 8 query rows.
// K/V tiles of 64 keys in XOR-swizzled smem (stride 64, conflict-free).
// Output written head-interleaved into g_att[B, T, D].
// ---------------------------------------------------------------------------
__device__ __forceinline__ float warp_max(float v) {
    #pragma unroll
    for (int o = 16; o > 0; o >>= 1) v = fmaxf(v, __shfl_xor_sync(0xFFFFFFFFu, v, o));
    return v;
}
__device__ __forceinline__ float warp_sum(float v) {
    #pragma unroll
    for (int o = 16; o > 0; o >>= 1) v += __shfl_xor_sync(0xFFFFFFFFu, v, o);
    return v;
}

__global__ __launch_bounds__(128, 4)
void attn_kernel()
{
    __shared__ float qs[32 * 64];
    __shared__ float ks[64 * 64];
    __shared__ float vs[64 * 64];
    __shared__ float ps[4 * 8 * 64];

    const int tid  = threadIdx.x;
    const int lane = tid & 31;
    const int wid  = tid >> 5;
    const int i0   = blockIdx.x * 32;
    const int h    = blockIdx.y;
    const int b    = blockIdx.z;

    const size_t base = (size_t)(b * CNH + h) * CT * CHD;
    const float* Q = g_q + base;
    const float* K = g_k + base;
    const float* V = g_v + base;
    const float slope = exp2f(-0.5f * (float)(h + 1));

    // Load Q tile [32][64] (linear smem; reads are warp-broadcast so no conflicts)
    for (int idx = tid; idx < 32 * 16; idx += 128) {
        const int row = idx >> 4;
        const int dq  = (idx & 15) << 2;
        *(float4*)&qs[row * 64 + dq] = *(const float4*)(Q + (size_t)(i0 + row) * CHD + dq);
    }

    const int r0 = wid * 8;
    float m[8], l[8], o0[8], o1[8];
    #pragma unroll
    for (int r = 0; r < 8; r++) { m[r] = -1e30f; l[r] = 0.f; o0[r] = 0.f; o1[r] = 0.f; }

    const int ihi = i0 + 31;
    for (int j0 = 0; j0 <= ihi; j0 += 64) {
        __syncthreads();   // protects qs (1st iter) and previous tile's ks/vs reads
        // Load K/V tiles, XOR-swizzled: elem (key, d) at [key*64 + (d ^ (key&31))]
        for (int idx = tid; idx < 64 * 16; idx += 128) {
            const int key  = idx >> 4;
            const int dq   = (idx & 15) << 2;
            const int klow = key & 31;
            const float4 kv = *(const float4*)(K + (size_t)(j0 + key) * CHD + dq);
            const float4 vv = *(const float4*)(V + (size_t)(j0 + key) * CHD + dq);
            ks[key * 64 + ((dq + 0) ^ klow)] = kv.x;
            ks[key * 64 + ((dq + 1) ^ klow)] = kv.y;
            ks[key * 64 + ((dq + 2) ^ klow)] = kv.z;
            ks[key * 64 + ((dq + 3) ^ klow)] = kv.w;
            vs[key * 64 + ((dq + 0) ^ klow)] = vv.x;
            vs[key * 64 + ((dq + 1) ^ klow)] = vv.y;
            vs[key * 64 + ((dq + 2) ^ klow)] = vv.z;
            vs[key * 64 + ((dq + 3) ^ klow)] = vv.w;
        }
        __syncthreads();

        // S = Q K^T : lane owns keys (lane) and (lane+32)
        float s0[8], s1[8];
        #pragma unroll
        for (int r = 0; r < 8; r++) { s0[r] = 0.f; s1[r] = 0.f; }
        #pragma unroll 8
        for (int d = 0; d < 64; d++) {
            const float k0 = ks[lane * 64 + (d ^ lane)];
            const float k1 = ks[(lane + 32) * 64 + (d ^ lane)];
            #pragma unroll
            for (int r = 0; r < 8; r++) {
                const float qv = qs[(r0 + r) * 64 + d];
                s0[r] += qv * k0;
                s1[r] += qv * k1;
            }
        }

        // ALiBi + causal mask + online softmax (per row, warp-wide)
        const float jj0 = (float)(j0 + lane);
        const float jj1 = (float)(j0 + lane + 32);
        #pragma unroll
        for (int r = 0; r < 8; r++) {
            const float fi = (float)(i0 + r0 + r);
            float a0 = s0[r] + slope * (jj0 - fi);
            float a1 = s1[r] + slope * (jj1 - fi);
            if (jj0 > fi) a0 = -1e30f;
            if (jj1 > fi) a1 = -1e30f;
            const float tmax = warp_max(fmaxf(a0, a1));
            const float mn = fmaxf(m[r], tmax);
            const float corr = __expf(m[r] - mn);
            const float p0 = __expf(a0 - mn);
            const float p1 = __expf(a1 - mn);
            const float rs = warp_sum(p0 + p1);
            l[r] = l[r] * corr + rs;
            o0[r] *= corr; o1[r] *= corr;
            m[r] = mn;
            ps[(wid * 8 + r) * 64 + lane]      = p0;
            ps[(wid * 8 + r) * 64 + lane + 32] = p1;
        }
        __syncwarp();

        // O += P V : lane owns output dims (lane) and (lane+32)
        #pragma unroll 8
        for (int key = 0; key < 64; key++) {
            const int kl = key & 31;
            const float v0 = vs[key * 64 + (lane ^ kl)];
            const float v1 = vs[key * 64 + ((lane + 32) ^ kl)];
            #pragma unroll
            for (int r = 0; r < 8; r++) {
                const float pv = ps[(wid * 8 + r) * 64 + key];
                o0[r] += pv * v0;
                o1[r] += pv * v1;
            }
        }
    }

    // Normalize and write to g_att[B, T, D] (head h occupies cols h*64..h*64+63)
    #pragma unroll
    for (int r = 0; r < 8; r++) {
        const float inv = 1.0f / l[r];
        const int t = i0 + r0 + r;
        const size_t oidx = (size_t)(b * CT + t) * CD + h * CHD;
        g_att[oidx + lane]      = o0[r] * inv;
        g_att[oidx + lane + 32] = o1[r] * inv;
    }
}

// ---------------------------------------------------------------------------
extern "C" void kernel_launch(void* const* d_in, const int* in_sizes, int n_in,
                              void* d_out, int out_size)
{
    (void)in_sizes; (void)n_in; (void)out_size;
    const float* x  = (const float*)d_in[0];
    const float* Wq = (const float*)d_in[1];
    const float* bq = (const float*)d_in[2];
    const float* Wk = (const float*)d_in[3];
    const float* bk = (const float*)d_in[4];
    const float* Wv = (const float*)d_in[5];
    const float* bv = (const float*)d_in[6];
    const float* Wp = (const float*)d_in[7];
    const float* bp = (const float*)d_in[8];

    float *qp, *kp, *vp, *ap;
    cudaGetSymbolAddress((void**)&qp, g_q);
    cudaGetSymbolAddress((void**)&kp, g_k);
    cudaGetSymbolAddress((void**)&vp, g_v);
    cudaGetSymbolAddress((void**)&ap, g_att);

    const dim3 ggrid(CD / 128, CM / 128);       // (8, 32)
    const float invs = 0.17677669529663687f;    // 1024^(-0.25)

    gemm_kernel<<<ggrid, 256>>>(x, Wq, bq, qp, invs, 1);
    gemm_kernel<<<ggrid, 256>>>(x, Wk, bk, kp, invs, 1);
    gemm_kernel<<<ggrid, 256>>>(x, Wv, bv, vp, 1.0f, 1);

    attn_kernel<<<dim3(CT / 32, CNH, CB), 128>>>();

    gemm_kernel<<<ggrid, 256>>>(ap, Wp, bp, (float*)d_out, 1.0f, 0);
}

// round 4
// speedup vs baseline: 1.4243x; 1.4243x over previous
#include <cuda_runtime.h>
#include <cuda_bf16.h>
#include <cstdint>

// Problem constants
#define CB 2
#define CT 2048
#define CD 1024
#define CNH 16
#define CHD 64
#define CM (CB*CT)              // 4096 rows

typedef __nv_bfloat16 bf16;

// ---------------------------------------------------------------------------
// Scratch (device globals)
// q/k/v/att stored [B*T, D] row-major (head h occupies cols h*64..h*64+63)
// ---------------------------------------------------------------------------
__device__ float g_q[CM*CD];
__device__ float g_k[CM*CD];
__device__ float g_v[CM*CD];
__device__ float g_att[CM*CD];
__device__ bf16  g_ahi[CM*CD];
__device__ bf16  g_alo[CM*CD];
__device__ bf16  g_whi[4*CD*CD];
__device__ bf16  g_wlo[4*CD*CD];

// ---------------------------------------------------------------------------
// fp32 -> bf16 hi/lo split (vectorized by 4)
// ---------------------------------------------------------------------------
__global__ __launch_bounds__(256)
void cvt_kernel(const float* __restrict__ s, bf16* __restrict__ hi,
                bf16* __restrict__ lo, int n4)
{
    int i = blockIdx.x * blockDim.x + threadIdx.x;
    if (i >= n4) return;
    float4 v = ((const float4*)s)[i];
    bf16 h0 = __float2bfloat16(v.x);
    bf16 h1 = __float2bfloat16(v.y);
    bf16 h2 = __float2bfloat16(v.z);
    bf16 h3 = __float2bfloat16(v.w);
    bf16 l0 = __float2bfloat16(v.x - __bfloat162float(h0));
    bf16 l1 = __float2bfloat16(v.y - __bfloat162float(h1));
    bf16 l2 = __float2bfloat16(v.z - __bfloat162float(h2));
    bf16 l3 = __float2bfloat16(v.w - __bfloat162float(h3));
    ((__nv_bfloat162*)hi)[2*i]   = __halves2bfloat162(h0, h1);
    ((__nv_bfloat162*)hi)[2*i+1] = __halves2bfloat162(h2, h3);
    ((__nv_bfloat162*)lo)[2*i]   = __halves2bfloat162(l0, l1);
    ((__nv_bfloat162*)lo)[2*i+1] = __halves2bfloat162(l2, l3);
}

// ---------------------------------------------------------------------------
// mma.sync bf16 GEMM with hi/lo 3-term fp32 emulation.
// C[M,N] = (Ahi+Alo)[M,K] @ (Bhi+Blo)[N,K]^T ; out = (C + bias) * scale
// BM=128, BN=128, BK=32, 256 threads = 8 warps (4M x 2N), warp tile 32x64.
// 4-stage cp.async pipeline. Swizzle: c16' = c16 ^ ((r>>1)&3) on 64B rows.
// ---------------------------------------------------------------------------
#define GBM 128
#define GBN 128
#define GBK 32
#define GSTAGES 4
#define GNKT (CD/GBK)                 // 32 k-tiles
#define PART_BYTES 8192               // 128 rows x 64B
#define STG_BYTES (4*PART_BYTES)      // Ahi|Alo|Bhi|Blo = 32KB
#define GSMEM (GSTAGES*STG_BYTES)     // 128KB

static __device__ __forceinline__ uint32_t swz(int r, int c16) {
    return (uint32_t)(r * 64 + ((c16 ^ ((r >> 1) & 3)) << 4));
}
static __device__ __forceinline__ void cp16(uint32_t d, const void* s) {
    asm volatile("cp.async.cg.shared.global [%0], [%1], 16;\n" :: "r"(d), "l"(s));
}
static __device__ __forceinline__ void cp_commit() {
    asm volatile("cp.async.commit_group;\n" ::: "memory");
}
template<int N> static __device__ __forceinline__ void cp_wait() {
    asm volatile("cp.async.wait_group %0;\n" :: "n"(N) : "memory");
}
static __device__ __forceinline__ void ldsm4(uint32_t& r0, uint32_t& r1,
                                             uint32_t& r2, uint32_t& r3, uint32_t a) {
    asm volatile("ldmatrix.sync.aligned.m8n8.x4.shared.b16 {%0,%1,%2,%3}, [%4];"
                 : "=r"(r0), "=r"(r1), "=r"(r2), "=r"(r3) : "r"(a));
}
static __device__ __forceinline__ void mma16816(float* c, const uint32_t* a,
                                                uint32_t b0, uint32_t b1) {
    asm volatile(
        "mma.sync.aligned.m16n8k16.row.col.f32.bf16.bf16.f32 "
        "{%0,%1,%2,%3}, {%4,%5,%6,%7}, {%8,%9}, {%0,%1,%2,%3};"
        : "+f"(c[0]), "+f"(c[1]), "+f"(c[2]), "+f"(c[3])
        : "r"(a[0]), "r"(a[1]), "r"(a[2]), "r"(a[3]), "r"(b0), "r"(b1));
}

static __device__ __forceinline__ void g_load_stage(
    uint32_t sbase, int kt, int tid,
    const bf16* __restrict__ Ah, const bf16* __restrict__ Al,
    const bf16* __restrict__ Bh, const bf16* __restrict__ Bl,
    int bm, int bn)
{
    const int k0 = kt * GBK;
    const bf16* srcs[4] = { Ah, Al, Bh, Bl };
    #pragma unroll
    for (int p = 0; p < 4; p++) {
        const int rowbase = (p < 2) ? bm : bn;
        const bf16* src = srcs[p];
        #pragma unroll
        for (int i = 0; i < 2; i++) {
            const int id = tid + i * 256;      // 0..511 chunk id
            const int r = id >> 2;
            const int c = id & 3;
            cp16(sbase + (uint32_t)p * PART_BYTES + swz(r, c),
                 src + (size_t)(rowbase + r) * CD + k0 + c * 8);
        }
    }
}

__global__ __launch_bounds__(256, 1)
void tc_gemm(const bf16* __restrict__ Ah, const bf16* __restrict__ Al,
             const bf16* __restrict__ Bh, const bf16* __restrict__ Bl,
             const float* __restrict__ bias, float* __restrict__ dst, float scale)
{
    extern __shared__ char dsm[];
    uint32_t sb;
    asm("{ .reg .u64 t; cvta.to.shared.u64 t, %1; cvt.u32.u64 %0, t; }" : "=r"(sb) : "l"(dsm));

    const int tid  = threadIdx.x;
    const int wid  = tid >> 5;
    const int lane = tid & 31;
    const int bm   = blockIdx.y * GBM;
    const int bn   = blockIdx.x * GBN;
    const int m0w  = (wid & 3) * 32;        // warp M offset
    const int n0w  = (wid >> 2) * 64;       // warp N offset

    float acc[2][8][4];
    #pragma unroll
    for (int i = 0; i < 2; i++)
        #pragma unroll
        for (int j = 0; j < 8; j++)
            #pragma unroll
            for (int k = 0; k < 4; k++) acc[i][j][k] = 0.f;

    // Preload stages 0..GSTAGES-2
    #pragma unroll
    for (int s = 0; s < GSTAGES - 1; s++) {
        g_load_stage(sb + s * STG_BYTES, s, tid, Ah, Al, Bh, Bl, bm, bn);
        cp_commit();
    }

    // ldmatrix per-thread address pieces (row within 16, chunk select)
    const int lr = lane & 15;         // row within m16/n16 block
    const int lc = lane >> 4;         // 0/1 -> k chunk within k16

    for (int kt = 0; kt < GNKT; kt++) {
        cp_wait<GSTAGES - 2>();
        __syncthreads();

        // Prefetch k-tile kt+GSTAGES-1 into buffer (kt-1)%GSTAGES (already consumed)
        if (kt + GSTAGES - 1 < GNKT) {
            g_load_stage(sb + ((kt + GSTAGES - 1) % GSTAGES) * STG_BYTES,
                         kt + GSTAGES - 1, tid, Ah, Al, Bh, Bl, bm, bn);
        }
        cp_commit();

        const uint32_t stg = sb + (uint32_t)(kt % GSTAGES) * STG_BYTES;
        #pragma unroll
        for (int ks = 0; ks < 2; ks++) {
            const int c16 = 2 * ks + lc;
            // A fragments (hi, lo) : 2 m16 blocks each
            uint32_t ah[2][4], al[2][4];
            #pragma unroll
            for (int mi = 0; mi < 2; mi++) {
                const int r = m0w + mi * 16 + lr;
                ldsm4(ah[mi][0], ah[mi][1], ah[mi][2], ah[mi][3],
                      stg + 0 * PART_BYTES + swz(r, c16));
                ldsm4(al[mi][0], al[mi][1], al[mi][2], al[mi][3],
                      stg + 1 * PART_BYTES + swz(r, c16));
            }
            // B fragments (hi, lo) : 4 n16 blocks -> 8 n8 frags each
            uint32_t bh[8][2], bl[8][2];
            #pragma unroll
            for (int bj = 0; bj < 4; bj++) {
                const int r = n0w + bj * 16 + lr;
                uint32_t r0, r1, r2, r3;
                ldsm4(r0, r1, r2, r3, stg + 2 * PART_BYTES + swz(r, c16));
                bh[bj*2][0]   = r0; bh[bj*2][1]   = r2;
                bh[bj*2+1][0] = r1; bh[bj*2+1][1] = r3;
                ldsm4(r0, r1, r2, r3, stg + 3 * PART_BYTES + swz(r, c16));
                bl[bj*2][0]   = r0; bl[bj*2][1]   = r2;
                bl[bj*2+1][0] = r1; bl[bj*2+1][1] = r3;
            }
            // 3-term mma
            #pragma unroll
            for (int mi = 0; mi < 2; mi++)
                #pragma unroll
                for (int nj = 0; nj < 8; nj++) {
                    mma16816(acc[mi][nj], ah[mi], bh[nj][0], bh[nj][1]);
                    mma16816(acc[mi][nj], ah[mi], bl[nj][0], bl[nj][1]);
                    mma16816(acc[mi][nj], al[mi], bh[nj][0], bh[nj][1]);
                }
        }
        __syncthreads();
    }

    // Epilogue: (acc + bias) * scale -> dst
    const int qr = lane >> 2;          // 0..7
    const int qc = (lane & 3) * 2;     // 0,2,4,6
    #pragma unroll
    for (int mi = 0; mi < 2; mi++) {
        #pragma unroll
        for (int nj = 0; nj < 8; nj++) {
            const int col = bn + n0w + nj * 8 + qc;
            const float b0 = __ldg(bias + col);
            const float b1 = __ldg(bias + col + 1);
            const int row0 = bm + m0w + mi * 16 + qr;
            float2 v0, v1;
            v0.x = (acc[mi][nj][0] + b0) * scale;
            v0.y = (acc[mi][nj][1] + b1) * scale;
            v1.x = (acc[mi][nj][2] + b0) * scale;
            v1.y = (acc[mi][nj][3] + b1) * scale;
            *(float2*)(dst + (size_t)row0 * CD + col)       = v0;
            *(float2*)(dst + (size_t)(row0 + 8) * CD + col) = v1;
        }
    }
}

// ---------------------------------------------------------------------------
// Flash attention with ALiBi + causal (fp32 SIMT — unchanged, passing)
// ---------------------------------------------------------------------------
__device__ __forceinline__ float warp_max(float v) {
    #pragma unroll
    for (int o = 16; o > 0; o >>= 1) v = fmaxf(v, __shfl_xor_sync(0xFFFFFFFFu, v, o));
    return v;
}
__device__ __forceinline__ float warp_sum(float v) {
    #pragma unroll
    for (int o = 16; o > 0; o >>= 1) v += __shfl_xor_sync(0xFFFFFFFFu, v, o);
    return v;
}

__global__ __launch_bounds__(128, 4)
void attn_kernel()
{
    __shared__ float qs[32 * 64];
    __shared__ float ks[64 * 64];
    __shared__ float vs[64 * 64];
    __shared__ float ps[4 * 8 * 64];

    const int tid  = threadIdx.x;
    const int lane = tid & 31;
    const int wid  = tid >> 5;
    const int i0   = blockIdx.x * 32;
    const int h    = blockIdx.y;
    const int b    = blockIdx.z;

    const size_t rowbase = (size_t)b * CT * CD + (size_t)h * CHD;
    const float* Q = g_q + rowbase;
    const float* K = g_k + rowbase;
    const float* V = g_v + rowbase;
    const float slope = exp2f(-0.5f * (float)(h + 1));

    for (int idx = tid; idx < 32 * 16; idx += 128) {
        const int row = idx >> 4;
        const int dq  = (idx & 15) << 2;
        *(float4*)&qs[row * 64 + dq] = *(const float4*)(Q + (size_t)(i0 + row) * CD + dq);
    }

    const int r0 = wid * 8;
    float m[8], l[8], o0[8], o1[8];
    #pragma unroll
    for (int r = 0; r < 8; r++) { m[r] = -1e30f; l[r] = 0.f; o0[r] = 0.f; o1[r] = 0.f; }

    const int ihi = i0 + 31;
    for (int j0 = 0; j0 <= ihi; j0 += 64) {
        __syncthreads();
        for (int idx = tid; idx < 64 * 16; idx += 128) {
            const int key  = idx >> 4;
            const int dq   = (idx & 15) << 2;
            const int klow = key & 31;
            const float4 kv = *(const float4*)(K + (size_t)(j0 + key) * CD + dq);
            const float4 vv = *(const float4*)(V + (size_t)(j0 + key) * CD + dq);
            ks[key * 64 + ((dq + 0) ^ klow)] = kv.x;
            ks[key * 64 + ((dq + 1) ^ klow)] = kv.y;
            ks[key * 64 + ((dq + 2) ^ klow)] = kv.z;
            ks[key * 64 + ((dq + 3) ^ klow)] = kv.w;
            vs[key * 64 + ((dq + 0) ^ klow)] = vv.x;
            vs[key * 64 + ((dq + 1) ^ klow)] = vv.y;
            vs[key * 64 + ((dq + 2) ^ klow)] = vv.z;
            vs[key * 64 + ((dq + 3) ^ klow)] = vv.w;
        }
        __syncthreads();

        float s0[8], s1[8];
        #pragma unroll
        for (int r = 0; r < 8; r++) { s0[r] = 0.f; s1[r] = 0.f; }
        #pragma unroll 8
        for (int d = 0; d < 64; d++) {
            const float k0 = ks[lane * 64 + (d ^ lane)];
            const float k1 = ks[(lane + 32) * 64 + (d ^ lane)];
            #pragma unroll
            for (int r = 0; r < 8; r++) {
                const float qv = qs[(r0 + r) * 64 + d];
                s0[r] += qv * k0;
                s1[r] += qv * k1;
            }
        }

        const float jj0 = (float)(j0 + lane);
        const float jj1 = (float)(j0 + lane + 32);
        #pragma unroll
        for (int r = 0; r < 8; r++) {
            const float fi = (float)(i0 + r0 + r);
            float a0 = s0[r] + slope * (jj0 - fi);
            float a1 = s1[r] + slope * (jj1 - fi);
            if (jj0 > fi) a0 = -1e30f;
            if (jj1 > fi) a1 = -1e30f;
            const float tmax = warp_max(fmaxf(a0, a1));
            const float mn = fmaxf(m[r], tmax);
            const float corr = __expf(m[r] - mn);
            const float p0 = __expf(a0 - mn);
            const float p1 = __expf(a1 - mn);
            const float rs = warp_sum(p0 + p1);
            l[r] = l[r] * corr + rs;
            o0[r] *= corr; o1[r] *= corr;
            m[r] = mn;
            ps[(wid * 8 + r) * 64 + lane]      = p0;
            ps[(wid * 8 + r) * 64 + lane + 32] = p1;
        }
        __syncwarp();

        #pragma unroll 8
        for (int key = 0; key < 64; key++) {
            const int kl = key & 31;
            const float v0 = vs[key * 64 + (lane ^ kl)];
            const float v1 = vs[key * 64 + ((lane + 32) ^ kl)];
            #pragma unroll
            for (int r = 0; r < 8; r++) {
                const float pv = ps[(wid * 8 + r) * 64 + key];
                o0[r] += pv * v0;
                o1[r] += pv * v1;
            }
        }
    }

    #pragma unroll
    for (int r = 0; r < 8; r++) {
        const float inv = 1.0f / l[r];
        const int t = i0 + r0 + r;
        const size_t oidx = (size_t)(b * CT + t) * CD + h * CHD;
        g_att[oidx + lane]      = o0[r] * inv;
        g_att[oidx + lane + 32] = o1[r] * inv;
    }
}

// ---------------------------------------------------------------------------
extern "C" void kernel_launch(void* const* d_in, const int* in_sizes, int n_in,
                              void* d_out, int out_size)
{
    (void)in_sizes; (void)n_in; (void)out_size;
    const float* x  = (const float*)d_in[0];
    const float* Wq = (const float*)d_in[1];
    const float* bq = (const float*)d_in[2];
    const float* Wk = (const float*)d_in[3];
    const float* bk = (const float*)d_in[4];
    const float* Wv = (const float*)d_in[5];
    const float* bv = (const float*)d_in[6];
    const float* Wp = (const float*)d_in[7];
    const float* bp = (const float*)d_in[8];

    float *qp, *kp, *vp, *ap;
    bf16 *ahi, *alo, *whi, *wlo;
    cudaGetSymbolAddress((void**)&qp,  g_q);
    cudaGetSymbolAddress((void**)&kp,  g_k);
    cudaGetSymbolAddress((void**)&vp,  g_v);
    cudaGetSymbolAddress((void**)&ap,  g_att);
    cudaGetSymbolAddress((void**)&ahi, g_ahi);
    cudaGetSymbolAddress((void**)&alo, g_alo);
    cudaGetSymbolAddress((void**)&whi, g_whi);
    cudaGetSymbolAddress((void**)&wlo, g_wlo);

    cudaFuncSetAttribute(tc_gemm, cudaFuncAttributeMaxDynamicSharedMemorySize, GSMEM);

    const int WN = CD * CD;
    const float invs = 0.17677669529663687f;   // 1024^(-0.25)

    cvt_kernel<<<(CM*CD/4 + 255)/256, 256>>>(x,  ahi, alo, CM*CD/4);
    cvt_kernel<<<(WN/4 + 255)/256, 256>>>(Wq, whi + 0*WN, wlo + 0*WN, WN/4);
    cvt_kernel<<<(WN/4 + 255)/256, 256>>>(Wk, whi + 1*WN, wlo + 1*WN, WN/4);
    cvt_kernel<<<(WN/4 + 255)/256, 256>>>(Wv, whi + 2*WN, wlo + 2*WN, WN/4);
    cvt_kernel<<<(WN/4 + 255)/256, 256>>>(Wp, whi + 3*WN, wlo + 3*WN, WN/4);

    const dim3 gg(CD / GBN, CM / GBM);   // (8, 32) = 256 CTAs
    tc_gemm<<<gg, 256, GSMEM>>>(ahi, alo, whi + 0*WN, wlo + 0*WN, bq, qp, invs);
    tc_gemm<<<gg, 256, GSMEM>>>(ahi, alo, whi + 1*WN, wlo + 1*WN, bk, kp, invs);
    tc_gemm<<<gg, 256, GSMEM>>>(ahi, alo, whi + 2*WN, wlo + 2*WN, bv, vp, 1.0f);

    attn_kernel<<<dim3(CT / 32, CNH, CB), 128>>>();

    cvt_kernel<<<(CM*CD/4 + 255)/256, 256>>>(ap, ahi, alo, CM*CD/4);
    tc_gemm<<<gg, 256, GSMEM>>>(ahi, alo, whi + 3*WN, wlo + 3*WN, bp, (float*)d_out, 1.0f);
}

// round 5
// speedup vs baseline: 2.8581x; 2.0067x over previous
#include <cuda_runtime.h>
#include <cuda_bf16.h>
#include <cstdint>

// Problem constants
#define CB 2
#define CT 2048
#define CD 1024
#define CNH 16
#define CHD 64
#define CM (CB*CT)              // 4096 rows

typedef __nv_bfloat16 bf16;

// ---------------------------------------------------------------------------
// Scratch (device globals)
// ---------------------------------------------------------------------------
__device__ bf16 g_ahi[CM*CD];           // hi/lo of GEMM A input (x, then att out)
__device__ bf16 g_alo[CM*CD];
__device__ bf16 g_whi[4*CD*CD];
__device__ bf16 g_wlo[4*CD*CD];
__device__ bf16 g_qhi[CM*CD];           // head-major [B,NH,T,64]
__device__ bf16 g_qlo[CM*CD];
__device__ bf16 g_khi[CM*CD];
__device__ bf16 g_klo[CM*CD];
__device__ bf16 g_vhi[CM*CD];
__device__ bf16 g_vlo[CM*CD];

// ---------------------------------------------------------------------------
// Common PTX helpers
// ---------------------------------------------------------------------------
static __device__ __forceinline__ void cp16(uint32_t d, const void* s) {
    asm volatile("cp.async.cg.shared.global [%0], [%1], 16;\n" :: "r"(d), "l"(s));
}
static __device__ __forceinline__ void cp_commit() {
    asm volatile("cp.async.commit_group;\n" ::: "memory");
}
template<int N> static __device__ __forceinline__ void cp_wait() {
    asm volatile("cp.async.wait_group %0;\n" :: "n"(N) : "memory");
}
static __device__ __forceinline__ void ldsm4(uint32_t& r0, uint32_t& r1,
                                             uint32_t& r2, uint32_t& r3, uint32_t a) {
    asm volatile("ldmatrix.sync.aligned.m8n8.x4.shared.b16 {%0,%1,%2,%3}, [%4];"
                 : "=r"(r0), "=r"(r1), "=r"(r2), "=r"(r3) : "r"(a));
}
static __device__ __forceinline__ void ldsm4t(uint32_t& r0, uint32_t& r1,
                                              uint32_t& r2, uint32_t& r3, uint32_t a) {
    asm volatile("ldmatrix.sync.aligned.m8n8.x4.trans.shared.b16 {%0,%1,%2,%3}, [%4];"
                 : "=r"(r0), "=r"(r1), "=r"(r2), "=r"(r3) : "r"(a));
}
static __device__ __forceinline__ void mma16816(float* c, const uint32_t* a,
                                                uint32_t b0, uint32_t b1) {
    asm volatile(
        "mma.sync.aligned.m16n8k16.row.col.f32.bf16.bf16.f32 "
        "{%0,%1,%2,%3}, {%4,%5,%6,%7}, {%8,%9}, {%0,%1,%2,%3};"
        : "+f"(c[0]), "+f"(c[1]), "+f"(c[2]), "+f"(c[3])
        : "r"(a[0]), "r"(a[1]), "r"(a[2]), "r"(a[3]), "r"(b0), "r"(b1));
}
static __device__ __forceinline__ uint32_t smem_u32(const void* p) {
    uint32_t r;
    asm("{ .reg .u64 t; cvta.to.shared.u64 t, %1; cvt.u32.u64 %0, t; }" : "=r"(r) : "l"(p));
    return r;
}

// ---------------------------------------------------------------------------
// fp32 -> bf16 hi/lo split (vectorized by 4)
// ---------------------------------------------------------------------------
__global__ __launch_bounds__(256)
void cvt_kernel(const float* __restrict__ s, bf16* __restrict__ hi,
                bf16* __restrict__ lo, int n4)
{
    int i = blockIdx.x * blockDim.x + threadIdx.x;
    if (i >= n4) return;
    float4 v = ((const float4*)s)[i];
    bf16 h0 = __float2bfloat16(v.x);
    bf16 h1 = __float2bfloat16(v.y);
    bf16 h2 = __float2bfloat16(v.z);
    bf16 h3 = __float2bfloat16(v.w);
    bf16 l0 = __float2bfloat16(v.x - __bfloat162float(h0));
    bf16 l1 = __float2bfloat16(v.y - __bfloat162float(h1));
    bf16 l2 = __float2bfloat16(v.z - __bfloat162float(h2));
    bf16 l3 = __float2bfloat16(v.w - __bfloat162float(h3));
    ((__nv_bfloat162*)hi)[2*i]   = __halves2bfloat162(h0, h1);
    ((__nv_bfloat162*)hi)[2*i+1] = __halves2bfloat162(h2, h3);
    ((__nv_bfloat162*)lo)[2*i]   = __halves2bfloat162(l0, l1);
    ((__nv_bfloat162*)lo)[2*i+1] = __halves2bfloat162(l2, l3);
}

// ---------------------------------------------------------------------------
// mma.sync bf16 GEMM with hi/lo 3-term fp32 emulation.
// mode 0: out = (C+bias)*scale as fp32 row-major [CM,CD] -> dst
// mode 1: out split hi/lo bf16, head-major [B,NH,T,64]   -> dhi,dlo
// ---------------------------------------------------------------------------
#define GBM 128
#define GBN 128
#define GBK 32
#define GSTAGES 4
#define GNKT (CD/GBK)
#define PART_BYTES 8192
#define STG_BYTES (4*PART_BYTES)
#define GSMEM (GSTAGES*STG_BYTES)

static __device__ __forceinline__ uint32_t swz(int r, int c16) {
    return (uint32_t)(r * 64 + ((c16 ^ ((r >> 1) & 3)) << 4));
}

static __device__ __forceinline__ void g_load_stage(
    uint32_t sbase, int kt, int tid,
    const bf16* __restrict__ Ah, const bf16* __restrict__ Al,
    const bf16* __restrict__ Bh, const bf16* __restrict__ Bl,
    int bm, int bn)
{
    const int k0 = kt * GBK;
    const bf16* srcs[4] = { Ah, Al, Bh, Bl };
    #pragma unroll
    for (int p = 0; p < 4; p++) {
        const int rowbase = (p < 2) ? bm : bn;
        const bf16* src = srcs[p];
        #pragma unroll
        for (int i = 0; i < 2; i++) {
            const int id = tid + i * 256;
            const int r = id >> 2;
            const int c = id & 3;
            cp16(sbase + (uint32_t)p * PART_BYTES + swz(r, c),
                 src + (size_t)(rowbase + r) * CD + k0 + c * 8);
        }
    }
}

__global__ __launch_bounds__(256, 1)
void tc_gemm(const bf16* __restrict__ Ah, const bf16* __restrict__ Al,
             const bf16* __restrict__ Bh, const bf16* __restrict__ Bl,
             const float* __restrict__ bias, float* __restrict__ dst,
             bf16* __restrict__ dhi, bf16* __restrict__ dlo,
             float scale, int mode)
{
    extern __shared__ char dsm[];
    uint32_t sb = smem_u32(dsm);

    const int tid  = threadIdx.x;
    const int wid  = tid >> 5;
    const int lane = tid & 31;
    const int bm   = blockIdx.y * GBM;
    const int bn   = blockIdx.x * GBN;
    const int m0w  = (wid & 3) * 32;
    const int n0w  = (wid >> 2) * 64;

    float acc[2][8][4];
    #pragma unroll
    for (int i = 0; i < 2; i++)
        #pragma unroll
        for (int j = 0; j < 8; j++)
            #pragma unroll
            for (int k = 0; k < 4; k++) acc[i][j][k] = 0.f;

    #pragma unroll
    for (int s = 0; s < GSTAGES - 1; s++) {
        g_load_stage(sb + s * STG_BYTES, s, tid, Ah, Al, Bh, Bl, bm, bn);
        cp_commit();
    }

    const int lr = lane & 15;
    const int lc = lane >> 4;

    for (int kt = 0; kt < GNKT; kt++) {
        cp_wait<GSTAGES - 2>();
        __syncthreads();

        if (kt + GSTAGES - 1 < GNKT) {
            g_load_stage(sb + ((kt + GSTAGES - 1) % GSTAGES) * STG_BYTES,
                         kt + GSTAGES - 1, tid, Ah, Al, Bh, Bl, bm, bn);
        }
        cp_commit();

        const uint32_t stg = sb + (uint32_t)(kt % GSTAGES) * STG_BYTES;
        #pragma unroll
        for (int ks = 0; ks < 2; ks++) {
            const int c16 = 2 * ks + lc;
            uint32_t ah[2][4], al[2][4];
            #pragma unroll
            for (int mi = 0; mi < 2; mi++) {
                const int r = m0w + mi * 16 + lr;
                ldsm4(ah[mi][0], ah[mi][1], ah[mi][2], ah[mi][3],
                      stg + 0 * PART_BYTES + swz(r, c16));
                ldsm4(al[mi][0], al[mi][1], al[mi][2], al[mi][3],
                      stg + 1 * PART_BYTES + swz(r, c16));
            }
            uint32_t bh[8][2], bl[8][2];
            #pragma unroll
            for (int bj = 0; bj < 4; bj++) {
                const int r = n0w + bj * 16 + lr;
                uint32_t r0, r1, r2, r3;
                ldsm4(r0, r1, r2, r3, stg + 2 * PART_BYTES + swz(r, c16));
                bh[bj*2][0]   = r0; bh[bj*2][1]   = r2;
                bh[bj*2+1][0] = r1; bh[bj*2+1][1] = r3;
                ldsm4(r0, r1, r2, r3, stg + 3 * PART_BYTES + swz(r, c16));
                bl[bj*2][0]   = r0; bl[bj*2][1]   = r2;
                bl[bj*2+1][0] = r1; bl[bj*2+1][1] = r3;
            }
            #pragma unroll
            for (int mi = 0; mi < 2; mi++)
                #pragma unroll
                for (int nj = 0; nj < 8; nj++) {
                    mma16816(acc[mi][nj], ah[mi], bh[nj][0], bh[nj][1]);
                    mma16816(acc[mi][nj], ah[mi], bl[nj][0], bl[nj][1]);
                    mma16816(acc[mi][nj], al[mi], bh[nj][0], bh[nj][1]);
                }
        }
        __syncthreads();
    }

    const int qr = lane >> 2;
    const int qc = (lane & 3) * 2;
    #pragma unroll
    for (int mi = 0; mi < 2; mi++) {
        #pragma unroll
        for (int nj = 0; nj < 8; nj++) {
            const int col = bn + n0w + nj * 8 + qc;
            const float b0 = __ldg(bias + col);
            const float b1 = __ldg(bias + col + 1);
            const int row0 = bm + m0w + mi * 16 + qr;
            float v00 = (acc[mi][nj][0] + b0) * scale;
            float v01 = (acc[mi][nj][1] + b1) * scale;
            float v10 = (acc[mi][nj][2] + b0) * scale;
            float v11 = (acc[mi][nj][3] + b1) * scale;
            if (mode == 0) {
                float2 a = make_float2(v00, v01);
                float2 b = make_float2(v10, v11);
                *(float2*)(dst + (size_t)row0 * CD + col)       = a;
                *(float2*)(dst + (size_t)(row0 + 8) * CD + col) = b;
            } else {
                // head-major hi/lo: [B,NH,T,64]
                const int h = col >> 6;
                const int d = col & 63;
                #pragma unroll
                for (int rr = 0; rr < 2; rr++) {
                    const int row = row0 + rr * 8;
                    const float x0 = rr ? v10 : v00;
                    const float x1 = rr ? v11 : v01;
                    const int bb = row >> 11;
                    const int t  = row & (CT - 1);
                    const size_t idx = ((size_t)((bb * CNH + h) * CT + t)) * 64 + d;
                    __nv_bfloat162 hh = __floats2bfloat162_rn(x0, x1);
                    __nv_bfloat162 ll = __floats2bfloat162_rn(
                        x0 - __low2float(hh), x1 - __high2float(hh));
                    *(__nv_bfloat162*)(dhi + idx) = hh;
                    *(__nv_bfloat162*)(dlo + idx) = ll;
                }
            }
        }
    }
}

// ---------------------------------------------------------------------------
// Tensor-core flash attention, ALiBi + causal, 3-term hi/lo for QK and PV.
// CTA: 64 q-rows (4 warps x m16), key tiles of 64, double-buffered KV stages.
// smem: Qhi 8K | Qlo 8K | 2 stages x (Khi|Klo|Vhi|Vlo = 32K) = 80KB dynamic.
// ---------------------------------------------------------------------------
#define A_QBYTES 16384
#define A_STG    32768
#define ASMEM    (A_QBYTES + 2*A_STG)

static __device__ __forceinline__ uint32_t swz128(int r, int c16) {
    return (uint32_t)(r * 128 + ((c16 ^ (r & 7)) << 4));
}

static __device__ __forceinline__ void a_load_kv(
    uint32_t stg, int tid,
    const bf16* __restrict__ kh, const bf16* __restrict__ kl,
    const bf16* __restrict__ vh, const bf16* __restrict__ vl, int j0)
{
    const bf16* arr[4] = { kh, kl, vh, vl };
    #pragma unroll
    for (int i = 0; i < 16; i++) {
        const int id = tid + i * 128;
        const int p = id >> 9;
        const int inner = id & 511;
        const int r = inner >> 3, c = inner & 7;
        cp16(stg + (uint32_t)p * 8192 + swz128(r, c),
             arr[p] + (size_t)(j0 + r) * 64 + c * 8);
    }
}

__global__ __launch_bounds__(128, 2)
void attn_mma(const bf16* __restrict__ qh_, const bf16* __restrict__ ql_,
              const bf16* __restrict__ kh_, const bf16* __restrict__ kl_,
              const bf16* __restrict__ vh_, const bf16* __restrict__ vl_,
              bf16* __restrict__ ohi, bf16* __restrict__ olo)
{
    extern __shared__ char dsm[];
    const uint32_t sb = smem_u32(dsm);
    const uint32_t sqh = sb, sql = sb + 8192;
    const uint32_t stg0 = sb + A_QBYTES, stg1 = stg0 + A_STG;

    const int tid  = threadIdx.x;
    const int lane = tid & 31;
    const int w    = tid >> 5;
    const int tq   = 31 - (int)blockIdx.x;     // longest CTAs first
    const int h    = blockIdx.y;
    const int b    = blockIdx.z;
    const int i0   = tq * 64;
    const int njt  = tq + 1;

    const size_t base = (size_t)(b * CNH + h) * CT * 64;
    const bf16* qh = qh_ + base; const bf16* ql = ql_ + base;
    const bf16* kh = kh_ + base; const bf16* kl = kl_ + base;
    const bf16* vh = vh_ + base; const bf16* vl = vl_ + base;

    const float slope = exp2f(-0.5f * (float)(h + 1));

    // Q tile load (group 0)
    #pragma unroll
    for (int i = 0; i < 8; i++) {
        const int id = tid + i * 128;
        const int hl = id >> 9;
        const int inner = id & 511;
        const int r = inner >> 3, c = inner & 7;
        cp16((hl ? sql : sqh) + swz128(r, c),
             (hl ? ql : qh) + (size_t)(i0 + r) * 64 + c * 8);
    }
    cp_commit();
    a_load_kv(stg0, tid, kh, kl, vh, vl, 0);
    cp_commit();

    cp_wait<1>();          // Q ready
    __syncthreads();

    // Q A-fragments, held in registers for the whole loop
    const int lr = lane & 15;
    const int lc = lane >> 4;
    uint32_t qfh[4][4], qfl[4][4];
    #pragma unroll
    for (int kk = 0; kk < 4; kk++) {
        const int r = w * 16 + lr;
        ldsm4(qfh[kk][0], qfh[kk][1], qfh[kk][2], qfh[kk][3], sqh + swz128(r, kk*2 + lc));
        ldsm4(qfl[kk][0], qfl[kk][1], qfl[kk][2], qfl[kk][3], sql + swz128(r, kk*2 + lc));
    }

    const int qr = lane >> 2;
    const int qc = (lane & 3) * 2;
    const int irow0 = i0 + w * 16 + qr;
    const int irow1 = irow0 + 8;

    float O[8][4];
    #pragma unroll
    for (int nj = 0; nj < 8; nj++)
        #pragma unroll
        for (int e = 0; e < 4; e++) O[nj][e] = 0.f;
    float m0 = -1e30f, m1 = -1e30f, l0 = 0.f, l1 = 0.f;

    for (int jt = 0; jt < njt; jt++) {
        if (jt + 1 < njt) {
            a_load_kv((jt & 1) ? stg0 : stg1, tid, kh, kl, vh, vl, (jt + 1) * 64);
            cp_commit();
            cp_wait<1>();
        } else {
            cp_wait<0>();
        }
        __syncthreads();

        const uint32_t stg = (jt & 1) ? stg1 : stg0;
        const uint32_t skh = stg, skl = stg + 8192, svh = stg + 16384, svl = stg + 24576;

        // ---- S = Q K^T (3-term) ----
        float S[8][4];
        #pragma unroll
        for (int nj = 0; nj < 8; nj++)
            #pragma unroll
            for (int e = 0; e < 4; e++) S[nj][e] = 0.f;

        #pragma unroll
        for (int kk = 0; kk < 4; kk++) {
            uint32_t bh[8][2], bl[8][2];
            #pragma unroll
            for (int n16 = 0; n16 < 4; n16++) {
                const int r = n16 * 16 + lr;
                uint32_t r0, r1, r2, r3;
                ldsm4(r0, r1, r2, r3, skh + swz128(r, kk*2 + lc));
                bh[n16*2][0]   = r0; bh[n16*2][1]   = r2;
                bh[n16*2+1][0] = r1; bh[n16*2+1][1] = r3;
                ldsm4(r0, r1, r2, r3, skl + swz128(r, kk*2 + lc));
                bl[n16*2][0]   = r0; bl[n16*2][1]   = r2;
                bl[n16*2+1][0] = r1; bl[n16*2+1][1] = r3;
            }
            #pragma unroll
            for (int nj = 0; nj < 8; nj++) {
                mma16816(S[nj], qfh[kk], bh[nj][0], bh[nj][1]);
                mma16816(S[nj], qfh[kk], bl[nj][0], bl[nj][1]);
                mma16816(S[nj], qfl[kk], bh[nj][0], bh[nj][1]);
            }
        }

        // ---- ALiBi + causal mask + online softmax ----
        const int jbase = jt * 64;
        const bool lastt = (jt == njt - 1);
        float tmax0 = -1e30f, tmax1 = -1e30f;
        #pragma unroll
        for (int nj = 0; nj < 8; nj++) {
            const int j0c = jbase + nj * 8 + qc;
            #pragma unroll
            for (int e = 0; e < 4; e++) {
                const int j = j0c + (e & 1);
                const int i = (e >> 1) ? irow1 : irow0;
                float s = S[nj][e] + slope * (float)(j - i);
                if (lastt && j > i) s = -1e30f;
                S[nj][e] = s;
            }
            tmax0 = fmaxf(tmax0, fmaxf(S[nj][0], S[nj][1]));
            tmax1 = fmaxf(tmax1, fmaxf(S[nj][2], S[nj][3]));
        }
        tmax0 = fmaxf(tmax0, __shfl_xor_sync(0xFFFFFFFFu, tmax0, 1));
        tmax0 = fmaxf(tmax0, __shfl_xor_sync(0xFFFFFFFFu, tmax0, 2));
        tmax1 = fmaxf(tmax1, __shfl_xor_sync(0xFFFFFFFFu, tmax1, 1));
        tmax1 = fmaxf(tmax1, __shfl_xor_sync(0xFFFFFFFFu, tmax1, 2));

        const float mn0 = fmaxf(m0, tmax0);
        const float mn1 = fmaxf(m1, tmax1);
        const float cr0 = __expf(m0 - mn0);
        const float cr1 = __expf(m1 - mn1);
        m0 = mn0; m1 = mn1;

        float ls0 = 0.f, ls1 = 0.f;
        #pragma unroll
        for (int nj = 0; nj < 8; nj++) {
            S[nj][0] = __expf(S[nj][0] - mn0);
            S[nj][1] = __expf(S[nj][1] - mn0);
            S[nj][2] = __expf(S[nj][2] - mn1);
            S[nj][3] = __expf(S[nj][3] - mn1);
            ls0 += S[nj][0] + S[nj][1];
            ls1 += S[nj][2] + S[nj][3];
        }
        l0 = l0 * cr0 + ls0;
        l1 = l1 * cr1 + ls1;
        #pragma unroll
        for (int nj = 0; nj < 8; nj++) {
            O[nj][0] *= cr0; O[nj][1] *= cr0;
            O[nj][2] *= cr1; O[nj][3] *= cr1;
        }

        // ---- O += P V (3-term) ----
        #pragma unroll
        for (int kk = 0; kk < 4; kk++) {
            // P A-frags for key chunk kk from S[2kk], S[2kk+1]
            uint32_t ph[4], pl[4];
            {
                const float* sA = S[2*kk];
                const float* sB = S[2*kk + 1];
                __nv_bfloat162 h2, l2;
                h2 = __floats2bfloat162_rn(sA[0], sA[1]);
                l2 = __floats2bfloat162_rn(sA[0] - __low2float(h2), sA[1] - __high2float(h2));
                ph[0] = *(uint32_t*)&h2; pl[0] = *(uint32_t*)&l2;
                h2 = __floats2bfloat162_rn(sA[2], sA[3]);
                l2 = __floats2bfloat162_rn(sA[2] - __low2float(h2), sA[3] - __high2float(h2));
                ph[1] = *(uint32_t*)&h2; pl[1] = *(uint32_t*)&l2;
                h2 = __floats2bfloat162_rn(sB[0], sB[1]);
                l2 = __floats2bfloat162_rn(sB[0] - __low2float(h2), sB[1] - __high2float(h2));
                ph[2] = *(uint32_t*)&h2; pl[2] = *(uint32_t*)&l2;
                h2 = __floats2bfloat162_rn(sB[2], sB[3]);
                l2 = __floats2bfloat162_rn(sB[2] - __low2float(h2), sB[3] - __high2float(h2));
                ph[3] = *(uint32_t*)&h2; pl[3] = *(uint32_t*)&l2;
            }
            uint32_t vhf[8][2], vlf[8][2];
            #pragma unroll
            for (int n16 = 0; n16 < 4; n16++) {
                const int r = kk * 16 + lr;
                uint32_t r0, r1, r2, r3;
                ldsm4t(r0, r1, r2, r3, svh + swz128(r, n16*2 + lc));
                vhf[n16*2][0]   = r0; vhf[n16*2][1]   = r1;
                vhf[n16*2+1][0] = r2; vhf[n16*2+1][1] = r3;
                ldsm4t(r0, r1, r2, r3, svl + swz128(r, n16*2 + lc));
                vlf[n16*2][0]   = r0; vlf[n16*2][1]   = r1;
                vlf[n16*2+1][0] = r2; vlf[n16*2+1][1] = r3;
            }
            #pragma unroll
            for (int nj = 0; nj < 8; nj++) {
                mma16816(O[nj], ph, vhf[nj][0], vhf[nj][1]);
                mma16816(O[nj], ph, vlf[nj][0], vlf[nj][1]);
                mma16816(O[nj], pl, vhf[nj][0], vhf[nj][1]);
            }
        }
        __syncthreads();   // stage may be overwritten next iteration
    }

    // ---- normalize + hi/lo store ----
    l0 += __shfl_xor_sync(0xFFFFFFFFu, l0, 1);
    l0 += __shfl_xor_sync(0xFFFFFFFFu, l0, 2);
    l1 += __shfl_xor_sync(0xFFFFFFFFu, l1, 1);
    l1 += __shfl_xor_sync(0xFFFFFFFFu, l1, 2);
    const float inv0 = 1.0f / l0;
    const float inv1 = 1.0f / l1;

    #pragma unroll
    for (int nj = 0; nj < 8; nj++) {
        const int col = h * 64 + nj * 8 + qc;
        const size_t idx0 = (size_t)(b * CT + irow0) * CD + col;
        const size_t idx1 = (size_t)(b * CT + irow1) * CD + col;
        float o00 = O[nj][0] * inv0, o01 = O[nj][1] * inv0;
        float o10 = O[nj][2] * inv1, o11 = O[nj][3] * inv1;
        __nv_bfloat162 h2, l2;
        h2 = __floats2bfloat162_rn(o00, o01);
        l2 = __floats2bfloat162_rn(o00 - __low2float(h2), o01 - __high2float(h2));
        *(__nv_bfloat162*)(ohi + idx0) = h2;
        *(__nv_bfloat162*)(olo + idx0) = l2;
        h2 = __floats2bfloat162_rn(o10, o11);
        l2 = __floats2bfloat162_rn(o10 - __low2float(h2), o11 - __high2float(h2));
        *(__nv_bfloat162*)(ohi + idx1) = h2;
        *(__nv_bfloat162*)(olo + idx1) = l2;
    }
}

// ---------------------------------------------------------------------------
extern "C" void kernel_launch(void* const* d_in, const int* in_sizes, int n_in,
                              void* d_out, int out_size)
{
    (void)in_sizes; (void)n_in; (void)out_size;
    const float* x  = (const float*)d_in[0];
    const float* Wq = (const float*)d_in[1];
    const float* bq = (const float*)d_in[2];
    const float* Wk = (const float*)d_in[3];
    const float* bk = (const float*)d_in[4];
    const float* Wv = (const float*)d_in[5];
    const float* bv = (const float*)d_in[6];
    const float* Wp = (const float*)d_in[7];
    const float* bp = (const float*)d_in[8];

    bf16 *ahi, *alo, *whi, *wlo, *qhi, *qlo, *khi, *klo, *vhi, *vlo;
    cudaGetSymbolAddress((void**)&ahi, g_ahi);
    cudaGetSymbolAddress((void**)&alo, g_alo);
    cudaGetSymbolAddress((void**)&whi, g_whi);
    cudaGetSymbolAddress((void**)&wlo, g_wlo);
    cudaGetSymbolAddress((void**)&qhi, g_qhi);
    cudaGetSymbolAddress((void**)&qlo, g_qlo);
    cudaGetSymbolAddress((void**)&khi, g_khi);
    cudaGetSymbolAddress((void**)&klo, g_klo);
    cudaGetSymbolAddress((void**)&vhi, g_vhi);
    cudaGetSymbolAddress((void**)&vlo, g_vlo);

    cudaFuncSetAttribute(tc_gemm,  cudaFuncAttributeMaxDynamicSharedMemorySize, GSMEM);
    cudaFuncSetAttribute(attn_mma, cudaFuncAttributeMaxDynamicSharedMemorySize, ASMEM);

    const int WN = CD * CD;
    const float invs = 0.17677669529663687f;   // 1024^(-0.25)

    cvt_kernel<<<(CM*CD/4 + 255)/256, 256>>>(x,  ahi, alo, CM*CD/4);
    cvt_kernel<<<(WN/4 + 255)/256, 256>>>(Wq, whi + 0*WN, wlo + 0*WN, WN/4);
    cvt_kernel<<<(WN/4 + 255)/256, 256>>>(Wk, whi + 1*WN, wlo + 1*WN, WN/4);
    cvt_kernel<<<(WN/4 + 255)/256, 256>>>(Wv, whi + 2*WN, wlo + 2*WN, WN/4);
    cvt_kernel<<<(WN/4 + 255)/256, 256>>>(Wp, whi + 3*WN, wlo + 3*WN, WN/4);

    const dim3 gg(CD / GBN, CM / GBM);   // (8, 32)
    tc_gemm<<<gg, 256, GSMEM>>>(ahi, alo, whi + 0*WN, wlo + 0*WN, bq,
                                nullptr, qhi, qlo, invs, 1);
    tc_gemm<<<gg, 256, GSMEM>>>(ahi, alo, whi + 1*WN, wlo + 1*WN, bk,
                                nullptr, khi, klo, invs, 1);
    tc_gemm<<<gg, 256, GSMEM>>>(ahi, alo, whi + 2*WN, wlo + 2*WN, bv,
                                nullptr, vhi, vlo, 1.0f, 1);

    attn_mma<<<dim3(32, CNH, CB), 128, ASMEM>>>(qhi, qlo, khi, klo, vhi, vlo, ahi, alo);

    tc_gemm<<<gg, 256, GSMEM>>>(ahi, alo, whi + 3*WN, wlo + 3*WN, bp,
                                (float*)d_out, nullptr, nullptr, 1.0f, 0);
}

// round 6
// speedup vs baseline: 3.0319x; 1.0608x over previous
#include <cuda_runtime.h>
#include <cuda_bf16.h>
#include <cstdint>

// Problem constants
#define CB 2
#define CT 2048
#define CD 1024
#define CNH 16
#define CHD 64
#define CM (CB*CT)              // 4096 rows

typedef __nv_bfloat16 bf16;

// ---------------------------------------------------------------------------
// Scratch (device globals)
// ---------------------------------------------------------------------------
__device__ bf16 g_ahi[CM*CD];           // hi/lo of GEMM A input (x, then att out)
__device__ bf16 g_alo[CM*CD];
__device__ bf16 g_whi[4*CD*CD];
__device__ bf16 g_wlo[4*CD*CD];
__device__ bf16 g_qhi[CM*CD];           // head-major [B,NH,T,64]
__device__ bf16 g_qlo[CM*CD];
__device__ bf16 g_khi[CM*CD];
__device__ bf16 g_klo[CM*CD];
__device__ bf16 g_vhi[CM*CD];
__device__ bf16 g_vlo[CM*CD];

// ---------------------------------------------------------------------------
// Common PTX helpers
// ---------------------------------------------------------------------------
static __device__ __forceinline__ void cp16(uint32_t d, const void* s) {
    asm volatile("cp.async.cg.shared.global [%0], [%1], 16;\n" :: "r"(d), "l"(s));
}
static __device__ __forceinline__ void cp_commit() {
    asm volatile("cp.async.commit_group;\n" ::: "memory");
}
template<int N> static __device__ __forceinline__ void cp_wait() {
    asm volatile("cp.async.wait_group %0;\n" :: "n"(N) : "memory");
}
static __device__ __forceinline__ void ldsm4(uint32_t& r0, uint32_t& r1,
                                             uint32_t& r2, uint32_t& r3, uint32_t a) {
    asm volatile("ldmatrix.sync.aligned.m8n8.x4.shared.b16 {%0,%1,%2,%3}, [%4];"
                 : "=r"(r0), "=r"(r1), "=r"(r2), "=r"(r3) : "r"(a));
}
static __device__ __forceinline__ void ldsm4t(uint32_t& r0, uint32_t& r1,
                                              uint32_t& r2, uint32_t& r3, uint32_t a) {
    asm volatile("ldmatrix.sync.aligned.m8n8.x4.trans.shared.b16 {%0,%1,%2,%3}, [%4];"
                 : "=r"(r0), "=r"(r1), "=r"(r2), "=r"(r3) : "r"(a));
}
static __device__ __forceinline__ void mma16816(float* c, const uint32_t* a,
                                                uint32_t b0, uint32_t b1) {
    asm volatile(
        "mma.sync.aligned.m16n8k16.row.col.f32.bf16.bf16.f32 "
        "{%0,%1,%2,%3}, {%4,%5,%6,%7}, {%8,%9}, {%0,%1,%2,%3};"
        : "+f"(c[0]), "+f"(c[1]), "+f"(c[2]), "+f"(c[3])
        : "r"(a[0]), "r"(a[1]), "r"(a[2]), "r"(a[3]), "r"(b0), "r"(b1));
}
static __device__ __forceinline__ uint32_t smem_u32(const void* p) {
    uint32_t r;
    asm("{ .reg .u64 t; cvta.to.shared.u64 t, %1; cvt.u32.u64 %0, t; }" : "=r"(r) : "l"(p));
    return r;
}

// ---------------------------------------------------------------------------
// fp32 -> bf16 hi/lo split (vectorized by 4)
// ---------------------------------------------------------------------------
__global__ __launch_bounds__(256)
void cvt_kernel(const float* __restrict__ s, bf16* __restrict__ hi,
                bf16* __restrict__ lo, int n4)
{
    int i = blockIdx.x * blockDim.x + threadIdx.x;
    if (i >= n4) return;
    float4 v = ((const float4*)s)[i];
    bf16 h0 = __float2bfloat16(v.x);
    bf16 h1 = __float2bfloat16(v.y);
    bf16 h2 = __float2bfloat16(v.z);
    bf16 h3 = __float2bfloat16(v.w);
    bf16 l0 = __float2bfloat16(v.x - __bfloat162float(h0));
    bf16 l1 = __float2bfloat16(v.y - __bfloat162float(h1));
    bf16 l2 = __float2bfloat16(v.z - __bfloat162float(h2));
    bf16 l3 = __float2bfloat16(v.w - __bfloat162float(h3));
    ((__nv_bfloat162*)hi)[2*i]   = __halves2bfloat162(h0, h1);
    ((__nv_bfloat162*)hi)[2*i+1] = __halves2bfloat162(h2, h3);
    ((__nv_bfloat162*)lo)[2*i]   = __halves2bfloat162(l0, l1);
    ((__nv_bfloat162*)lo)[2*i+1] = __halves2bfloat162(l2, l3);
}

// ---------------------------------------------------------------------------
// mma.sync bf16 GEMM with hi/lo 3-term fp32 emulation.
// mode 0: out = (C+bias)*scale as fp32 row-major [CM,CD] -> dst
// mode 1: out split hi/lo bf16, head-major [B,NH,T,64]   -> dhi,dlo
// 3 stages x 32KB = 96KB smem -> 2 CTAs/SM; ONE __syncthreads per k-tile.
// ---------------------------------------------------------------------------
#define GBM 128
#define GBN 128
#define GBK 32
#define GSTAGES 3
#define GNKT (CD/GBK)
#define PART_BYTES 8192
#define STG_BYTES (4*PART_BYTES)
#define GSMEM (GSTAGES*STG_BYTES)     // 96KB

static __device__ __forceinline__ uint32_t swz(int r, int c16) {
    return (uint32_t)(r * 64 + ((c16 ^ ((r >> 1) & 3)) << 4));
}

static __device__ __forceinline__ void g_load_stage(
    uint32_t sbase, int kt, int tid,
    const bf16* __restrict__ Ah, const bf16* __restrict__ Al,
    const bf16* __restrict__ Bh, const bf16* __restrict__ Bl,
    int bm, int bn)
{
    const int k0 = kt * GBK;
    const bf16* srcs[4] = { Ah, Al, Bh, Bl };
    #pragma unroll
    for (int p = 0; p < 4; p++) {
        const int rowbase = (p < 2) ? bm : bn;
        const bf16* src = srcs[p];
        #pragma unroll
        for (int i = 0; i < 2; i++) {
            const int id = tid + i * 256;
            const int r = id >> 2;
            const int c = id & 3;
            cp16(sbase + (uint32_t)p * PART_BYTES + swz(r, c),
                 src + (size_t)(rowbase + r) * CD + k0 + c * 8);
        }
    }
}

__global__ __launch_bounds__(256, 2)
void tc_gemm(const bf16* __restrict__ Ah, const bf16* __restrict__ Al,
             const bf16* __restrict__ Bh, const bf16* __restrict__ Bl,
             const float* __restrict__ bias, float* __restrict__ dst,
             bf16* __restrict__ dhi, bf16* __restrict__ dlo,
             float scale, int mode)
{
    extern __shared__ char dsm[];
    uint32_t sb = smem_u32(dsm);

    const int tid  = threadIdx.x;
    const int wid  = tid >> 5;
    const int lane = tid & 31;
    const int bm   = blockIdx.y * GBM;
    const int bn   = blockIdx.x * GBN;
    const int m0w  = (wid & 3) * 32;
    const int n0w  = (wid >> 2) * 64;

    float acc[2][8][4];
    #pragma unroll
    for (int i = 0; i < 2; i++)
        #pragma unroll
        for (int j = 0; j < 8; j++)
            #pragma unroll
            for (int k = 0; k < 4; k++) acc[i][j][k] = 0.f;

    // Preload stages 0,1
    #pragma unroll
    for (int s = 0; s < GSTAGES - 1; s++) {
        g_load_stage(sb + s * STG_BYTES, s, tid, Ah, Al, Bh, Bl, bm, bn);
        cp_commit();
    }

    const int lr = lane & 15;
    const int lc = lane >> 4;

    for (int kt = 0; kt < GNKT; kt++) {
        cp_wait<1>();              // stage kt complete (kt+1 may be in flight)
        __syncthreads();           // all warps done with stage (kt-1)%3

        // Prefetch stage kt+2 into buffer (kt+2)%3 == (kt-1)%3 (consumed last iter)
        if (kt + 2 < GNKT) {
            g_load_stage(sb + ((kt + 2) % GSTAGES) * STG_BYTES,
                         kt + 2, tid, Ah, Al, Bh, Bl, bm, bn);
        }
        cp_commit();

        const uint32_t stg = sb + (uint32_t)(kt % GSTAGES) * STG_BYTES;
        #pragma unroll
        for (int ks = 0; ks < 2; ks++) {
            const int c16 = 2 * ks + lc;
            uint32_t ah[2][4], al[2][4];
            #pragma unroll
            for (int mi = 0; mi < 2; mi++) {
                const int r = m0w + mi * 16 + lr;
                ldsm4(ah[mi][0], ah[mi][1], ah[mi][2], ah[mi][3],
                      stg + 0 * PART_BYTES + swz(r, c16));
                ldsm4(al[mi][0], al[mi][1], al[mi][2], al[mi][3],
                      stg + 1 * PART_BYTES + swz(r, c16));
            }
            uint32_t bh[8][2], bl[8][2];
            #pragma unroll
            for (int bj = 0; bj < 4; bj++) {
                const int r = n0w + bj * 16 + lr;
                uint32_t r0, r1, r2, r3;
                ldsm4(r0, r1, r2, r3, stg + 2 * PART_BYTES + swz(r, c16));
                bh[bj*2][0]   = r0; bh[bj*2][1]   = r2;
                bh[bj*2+1][0] = r1; bh[bj*2+1][1] = r3;
                ldsm4(r0, r1, r2, r3, stg + 3 * PART_BYTES + swz(r, c16));
                bl[bj*2][0]   = r0; bl[bj*2][1]   = r2;
                bl[bj*2+1][0] = r1; bl[bj*2+1][1] = r3;
            }
            #pragma unroll
            for (int mi = 0; mi < 2; mi++)
                #pragma unroll
                for (int nj = 0; nj < 8; nj++) {
                    mma16816(acc[mi][nj], ah[mi], bh[nj][0], bh[nj][1]);
                    mma16816(acc[mi][nj], ah[mi], bl[nj][0], bl[nj][1]);
                    mma16816(acc[mi][nj], al[mi], bh[nj][0], bh[nj][1]);
                }
        }
    }

    const int qr = lane >> 2;
    const int qc = (lane & 3) * 2;
    #pragma unroll
    for (int mi = 0; mi < 2; mi++) {
        #pragma unroll
        for (int nj = 0; nj < 8; nj++) {
            const int col = bn + n0w + nj * 8 + qc;
            const float b0 = __ldg(bias + col);
            const float b1 = __ldg(bias + col + 1);
            const int row0 = bm + m0w + mi * 16 + qr;
            float v00 = (acc[mi][nj][0] + b0) * scale;
            float v01 = (acc[mi][nj][1] + b1) * scale;
            float v10 = (acc[mi][nj][2] + b0) * scale;
            float v11 = (acc[mi][nj][3] + b1) * scale;
            if (mode == 0) {
                float2 a = make_float2(v00, v01);
                float2 b = make_float2(v10, v11);
                *(float2*)(dst + (size_t)row0 * CD + col)       = a;
                *(float2*)(dst + (size_t)(row0 + 8) * CD + col) = b;
            } else {
                const int h = col >> 6;
                const int d = col & 63;
                #pragma unroll
                for (int rr = 0; rr < 2; rr++) {
                    const int row = row0 + rr * 8;
                    const float x0 = rr ? v10 : v00;
                    const float x1 = rr ? v11 : v01;
                    const int bb = row >> 11;
                    const int t  = row & (CT - 1);
                    const size_t idx = ((size_t)((bb * CNH + h) * CT + t)) * 64 + d;
                    __nv_bfloat162 hh = __floats2bfloat162_rn(x0, x1);
                    __nv_bfloat162 ll = __floats2bfloat162_rn(
                        x0 - __low2float(hh), x1 - __high2float(hh));
                    *(__nv_bfloat162*)(dhi + idx) = hh;
                    *(__nv_bfloat162*)(dlo + idx) = ll;
                }
            }
        }
    }
}

// ---------------------------------------------------------------------------
// Tensor-core flash attention, ALiBi + causal, 3-term hi/lo for QK and PV.
// CTA: 64 q-rows (4 warps x m16), key tiles of 64, double-buffered KV stages.
// ---------------------------------------------------------------------------
#define A_QBYTES 16384
#define A_STG    32768
#define ASMEM    (A_QBYTES + 2*A_STG)

static __device__ __forceinline__ uint32_t swz128(int r, int c16) {
    return (uint32_t)(r * 128 + ((c16 ^ (r & 7)) << 4));
}

static __device__ __forceinline__ void a_load_kv(
    uint32_t stg, int tid,
    const bf16* __restrict__ kh, const bf16* __restrict__ kl,
    const bf16* __restrict__ vh, const bf16* __restrict__ vl, int j0)
{
    const bf16* arr[4] = { kh, kl, vh, vl };
    #pragma unroll
    for (int i = 0; i < 16; i++) {
        const int id = tid + i * 128;
        const int p = id >> 9;
        const int inner = id & 511;
        const int r = inner >> 3, c = inner & 7;
        cp16(stg + (uint32_t)p * 8192 + swz128(r, c),
             arr[p] + (size_t)(j0 + r) * 64 + c * 8);
    }
}

__global__ __launch_bounds__(128, 2)
void attn_mma(const bf16* __restrict__ qh_, const bf16* __restrict__ ql_,
              const bf16* __restrict__ kh_, const bf16* __restrict__ kl_,
              const bf16* __restrict__ vh_, const bf16* __restrict__ vl_,
              bf16* __restrict__ ohi, bf16* __restrict__ olo)
{
    extern __shared__ char dsm[];
    const uint32_t sb = smem_u32(dsm);
    const uint32_t sqh = sb, sql = sb + 8192;
    const uint32_t stg0 = sb + A_QBYTES, stg1 = stg0 + A_STG;

    const int tid  = threadIdx.x;
    const int lane = tid & 31;
    const int w    = tid >> 5;
    const int tq   = 31 - (int)blockIdx.x;     // longest CTAs first
    const int h    = blockIdx.y;
    const int b    = blockIdx.z;
    const int i0   = tq * 64;
    const int njt  = tq + 1;

    const size_t base = (size_t)(b * CNH + h) * CT * 64;
    const bf16* qh = qh_ + base; const bf16* ql = ql_ + base;
    const bf16* kh = kh_ + base; const bf16* kl = kl_ + base;
    const bf16* vh = vh_ + base; const bf16* vl = vl_ + base;

    const float slope = exp2f(-0.5f * (float)(h + 1));

    // Q tile load
    #pragma unroll
    for (int i = 0; i < 8; i++) {
        const int id = tid + i * 128;
        const int hl = id >> 9;
        const int inner = id & 511;
        const int r = inner >> 3, c = inner & 7;
        cp16((hl ? sql : sqh) + swz128(r, c),
             (hl ? ql : qh) + (size_t)(i0 + r) * 64 + c * 8);
    }
    cp_commit();
    a_load_kv(stg0, tid, kh, kl, vh, vl, 0);
    cp_commit();

    cp_wait<1>();          // Q ready
    __syncthreads();

    const int lr = lane & 15;
    const int lc = lane >> 4;
    uint32_t qfh[4][4], qfl[4][4];
    #pragma unroll
    for (int kk = 0; kk < 4; kk++) {
        const int r = w * 16 + lr;
        ldsm4(qfh[kk][0], qfh[kk][1], qfh[kk][2], qfh[kk][3], sqh + swz128(r, kk*2 + lc));
        ldsm4(qfl[kk][0], qfl[kk][1], qfl[kk][2], qfl[kk][3], sql + swz128(r, kk*2 + lc));
    }

    const int qr = lane >> 2;
    const int qc = (lane & 3) * 2;
    const int irow0 = i0 + w * 16 + qr;
    const int irow1 = irow0 + 8;

    float O[8][4];
    #pragma unroll
    for (int nj = 0; nj < 8; nj++)
        #pragma unroll
        for (int e = 0; e < 4; e++) O[nj][e] = 0.f;
    float m0 = -1e30f, m1 = -1e30f, l0 = 0.f, l1 = 0.f;

    for (int jt = 0; jt < njt; jt++) {
        if (jt + 1 < njt) {
            a_load_kv((jt & 1) ? stg0 : stg1, tid, kh, kl, vh, vl, (jt + 1) * 64);
            cp_commit();
            cp_wait<1>();
        } else {
            cp_wait<0>();
        }
        __syncthreads();

        const uint32_t stg = (jt & 1) ? stg1 : stg0;
        const uint32_t skh = stg, skl = stg + 8192, svh = stg + 16384, svl = stg + 24576;

        // ---- S = Q K^T (3-term) ----
        float S[8][4];
        #pragma unroll
        for (int nj = 0; nj < 8; nj++)
            #pragma unroll
            for (int e = 0; e < 4; e++) S[nj][e] = 0.f;

        #pragma unroll
        for (int kk = 0; kk < 4; kk++) {
            uint32_t bh[8][2], bl[8][2];
            #pragma unroll
            for (int n16 = 0; n16 < 4; n16++) {
                const int r = n16 * 16 + lr;
                uint32_t r0, r1, r2, r3;
                ldsm4(r0, r1, r2, r3, skh + swz128(r, kk*2 + lc));
                bh[n16*2][0]   = r0; bh[n16*2][1]   = r2;
                bh[n16*2+1][0] = r1; bh[n16*2+1][1] = r3;
                ldsm4(r0, r1, r2, r3, skl + swz128(r, kk*2 + lc));
                bl[n16*2][0]   = r0; bl[n16*2][1]   = r2;
                bl[n16*2+1][0] = r1; bl[n16*2+1][1] = r3;
            }
            #pragma unroll
            for (int nj = 0; nj < 8; nj++) {
                mma16816(S[nj], qfh[kk], bh[nj][0], bh[nj][1]);
                mma16816(S[nj], qfh[kk], bl[nj][0], bl[nj][1]);
                mma16816(S[nj], qfl[kk], bh[nj][0], bh[nj][1]);
            }
        }

        // ---- ALiBi + causal + online softmax ----
        const int jbase = jt * 64;
        const bool lastt = (jt == njt - 1);
        float tmax0 = -1e30f, tmax1 = -1e30f;
        #pragma unroll
        for (int nj = 0; nj < 8; nj++) {
            const int j0c = jbase + nj * 8 + qc;
            #pragma unroll
            for (int e = 0; e < 4; e++) {
                const int j = j0c + (e & 1);
                const int i = (e >> 1) ? irow1 : irow0;
                float s = S[nj][e] + slope * (float)(j - i);
                if (lastt && j > i) s = -1e30f;
                S[nj][e] = s;
            }
            tmax0 = fmaxf(tmax0, fmaxf(S[nj][0], S[nj][1]));
            tmax1 = fmaxf(tmax1, fmaxf(S[nj][2], S[nj][3]));
        }
        tmax0 = fmaxf(tmax0, __shfl_xor_sync(0xFFFFFFFFu, tmax0, 1));
        tmax0 = fmaxf(tmax0, __shfl_xor_sync(0xFFFFFFFFu, tmax0, 2));
        tmax1 = fmaxf(tmax1, __shfl_xor_sync(0xFFFFFFFFu, tmax1, 1));
        tmax1 = fmaxf(tmax1, __shfl_xor_sync(0xFFFFFFFFu, tmax1, 2));

        const float mn0 = fmaxf(m0, tmax0);
        const float mn1 = fmaxf(m1, tmax1);
        const float cr0 = __expf(m0 - mn0);
        const float cr1 = __expf(m1 - mn1);
        m0 = mn0; m1 = mn1;

        float ls0 = 0.f, ls1 = 0.f;
        #pragma unroll
        for (int nj = 0; nj < 8; nj++) {
            S[nj][0] = __expf(S[nj][0] - mn0);
            S[nj][1] = __expf(S[nj][1] - mn0);
            S[nj][2] = __expf(S[nj][2] - mn1);
            S[nj][3] = __expf(S[nj][3] - mn1);
            ls0 += S[nj][0] + S[nj][1];
            ls1 += S[nj][2] + S[nj][3];
        }
        l0 = l0 * cr0 + ls0;
        l1 = l1 * cr1 + ls1;
        #pragma unroll
        for (int nj = 0; nj < 8; nj++) {
            O[nj][0] *= cr0; O[nj][1] *= cr0;
            O[nj][2] *= cr1; O[nj][3] *= cr1;
        }

        // ---- O += P V (3-term) ----
        #pragma unroll
        for (int kk = 0; kk < 4; kk++) {
            uint32_t ph[4], pl[4];
            {
                const float* sA = S[2*kk];
                const float* sB = S[2*kk + 1];
                __nv_bfloat162 h2, l2;
                h2 = __floats2bfloat162_rn(sA[0], sA[1]);
                l2 = __floats2bfloat162_rn(sA[0] - __low2float(h2), sA[1] - __high2float(h2));
                ph[0] = *(uint32_t*)&h2; pl[0] = *(uint32_t*)&l2;
                h2 = __floats2bfloat162_rn(sA[2], sA[3]);
                l2 = __floats2bfloat162_rn(sA[2] - __low2float(h2), sA[3] - __high2float(h2));
                ph[1] = *(uint32_t*)&h2; pl[1] = *(uint32_t*)&l2;
                h2 = __floats2bfloat162_rn(sB[0], sB[1]);
                l2 = __floats2bfloat162_rn(sB[0] - __low2float(h2), sB[1] - __high2float(h2));
                ph[2] = *(uint32_t*)&h2; pl[2] = *(uint32_t*)&l2;
                h2 = __floats2bfloat162_rn(sB[2], sB[3]);
                l2 = __floats2bfloat162_rn(sB[2] - __low2float(h2), sB[3] - __high2float(h2));
                ph[3] = *(uint32_t*)&h2; pl[3] = *(uint32_t*)&l2;
            }
            uint32_t vhf[8][2], vlf[8][2];
            #pragma unroll
            for (int n16 = 0; n16 < 4; n16++) {
                const int r = kk * 16 + lr;
                uint32_t r0, r1, r2, r3;
                ldsm4t(r0, r1, r2, r3, svh + swz128(r, n16*2 + lc));
                vhf[n16*2][0]   = r0; vhf[n16*2][1]   = r1;
                vhf[n16*2+1][0] = r2; vhf[n16*2+1][1] = r3;
                ldsm4t(r0, r1, r2, r3, svl + swz128(r, n16*2 + lc));
                vlf[n16*2][0]   = r0; vlf[n16*2][1]   = r1;
                vlf[n16*2+1][0] = r2; vlf[n16*2+1][1] = r3;
            }
            #pragma unroll
            for (int nj = 0; nj < 8; nj++) {
                mma16816(O[nj], ph, vhf[nj][0], vhf[nj][1]);
                mma16816(O[nj], ph, vlf[nj][0], vlf[nj][1]);
                mma16816(O[nj], pl, vhf[nj][0], vhf[nj][1]);
            }
        }
        __syncthreads();
    }

    // ---- normalize + hi/lo store ----
    l0 += __shfl_xor_sync(0xFFFFFFFFu, l0, 1);
    l0 += __shfl_xor_sync(0xFFFFFFFFu, l0, 2);
    l1 += __shfl_xor_sync(0xFFFFFFFFu, l1, 1);
    l1 += __shfl_xor_sync(0xFFFFFFFFu, l1, 2);
    const float inv0 = 1.0f / l0;
    const float inv1 = 1.0f / l1;

    #pragma unroll
    for (int nj = 0; nj < 8; nj++) {
        const int col = h * 64 + nj * 8 + qc;
        const size_t idx0 = (size_t)(b * CT + irow0) * CD + col;
        const size_t idx1 = (size_t)(b * CT + irow1) * CD + col;
        float o00 = O[nj][0] * inv0, o01 = O[nj][1] * inv0;
        float o10 = O[nj][2] * inv1, o11 = O[nj][3] * inv1;
        __nv_bfloat162 h2, l2;
        h2 = __floats2bfloat162_rn(o00, o01);
        l2 = __floats2bfloat162_rn(o00 - __low2float(h2), o01 - __high2float(h2));
        *(__nv_bfloat162*)(ohi + idx0) = h2;
        *(__nv_bfloat162*)(olo + idx0) = l2;
        h2 = __floats2bfloat162_rn(o10, o11);
        l2 = __floats2bfloat162_rn(o10 - __low2float(h2), o11 - __high2float(h2));
        *(__nv_bfloat162*)(ohi + idx1) = h2;
        *(__nv_bfloat162*)(olo + idx1) = l2;
    }
}

// ---------------------------------------------------------------------------
extern "C" void kernel_launch(void* const* d_in, const int* in_sizes, int n_in,
                              void* d_out, int out_size)
{
    (void)in_sizes; (void)n_in; (void)out_size;
    const float* x  = (const float*)d_in[0];
    const float* Wq = (const float*)d_in[1];
    const float* bq = (const float*)d_in[2];
    const float* Wk = (const float*)d_in[3];
    const float* bk = (const float*)d_in[4];
    const float* Wv = (const float*)d_in[5];
    const float* bv = (const float*)d_in[6];
    const float* Wp = (const float*)d_in[7];
    const float* bp = (const float*)d_in[8];

    bf16 *ahi, *alo, *whi, *wlo, *qhi, *qlo, *khi, *klo, *vhi, *vlo;
    cudaGetSymbolAddress((void**)&ahi, g_ahi);
    cudaGetSymbolAddress((void**)&alo, g_alo);
    cudaGetSymbolAddress((void**)&whi, g_whi);
    cudaGetSymbolAddress((void**)&wlo, g_wlo);
    cudaGetSymbolAddress((void**)&qhi, g_qhi);
    cudaGetSymbolAddress((void**)&qlo, g_qlo);
    cudaGetSymbolAddress((void**)&khi, g_khi);
    cudaGetSymbolAddress((void**)&klo, g_klo);
    cudaGetSymbolAddress((void**)&vhi, g_vhi);
    cudaGetSymbolAddress((void**)&vlo, g_vlo);

    cudaFuncSetAttribute(tc_gemm,  cudaFuncAttributeMaxDynamicSharedMemorySize, GSMEM);
    cudaFuncSetAttribute(attn_mma, cudaFuncAttributeMaxDynamicSharedMemorySize, ASMEM);

    const int WN = CD * CD;
    const float invs = 0.17677669529663687f;   // 1024^(-0.25)

    cvt_kernel<<<(CM*CD/4 + 255)/256, 256>>>(x,  ahi, alo, CM*CD/4);
    cvt_kernel<<<(WN/4 + 255)/256, 256>>>(Wq, whi + 0*WN, wlo + 0*WN, WN/4);
    cvt_kernel<<<(WN/4 + 255)/256, 256>>>(Wk, whi + 1*WN, wlo + 1*WN, WN/4);
    cvt_kernel<<<(WN/4 + 255)/256, 256>>>(Wv, whi + 2*WN, wlo + 2*WN, WN/4);
    cvt_kernel<<<(WN/4 + 255)/256, 256>>>(Wp, whi + 3*WN, wlo + 3*WN, WN/4);

    const dim3 gg(CD / GBN, CM / GBM);   // (8, 32)
    tc_gemm<<<gg, 256, GSMEM>>>(ahi, alo, whi + 0*WN, wlo + 0*WN, bq,
                                nullptr, qhi, qlo, invs, 1);
    tc_gemm<<<gg, 256, GSMEM>>>(ahi, alo, whi + 1*WN, wlo + 1*WN, bk,
                                nullptr, khi, klo, invs, 1);
    tc_gemm<<<gg, 256, GSMEM>>>(ahi, alo, whi + 2*WN, wlo + 2*WN, bv,
                                nullptr, vhi, vlo, 1.0f, 1);

    attn_mma<<<dim3(32, CNH, CB), 128, ASMEM>>>(qhi, qlo, khi, klo, vhi, vlo, ahi, alo);

    tc_gemm<<<gg, 256, GSMEM>>>(ahi, alo, whi + 3*WN, wlo + 3*WN, bp,
                                (float*)d_out, nullptr, nullptr, 1.0f, 0);
}